// round 2
// baseline (speedup 1.0000x reference)
#include <cuda_runtime.h>

#define NUM_ENT 50000
#define NUM_REL 237
#define REXT    238
#define D       64
#define BN_EPS  1e-5f

// ---------------- device scratch (no allocations allowed) ----------------
__device__ float g_SO[NUM_ENT * D];      // scatter sum, mask=1 edges
__device__ float g_SI[NUM_ENT * D];      // scatter sum, mask=0 edges
__device__ float g_ntmp[NUM_ENT * D];    // pre-BN node output
__device__ float g_nbuf[NUM_ENT * D];    // post-layer-0 node features
__device__ float g_rext[REXT * D];       // [r ; loop_rel]
__device__ float g_rnext[NUM_REL * D];   // layer-0 relation output
__device__ float g_sum[D], g_sumsq[D];   // BN stats accumulators
__device__ float g_scale[D], g_shift[D]; // folded BN affine

// ---------------- zero scatter buffers + stats ----------------
__global__ void zero_kernel() {
    const int n4 = NUM_ENT * D / 4;
    float4 z = make_float4(0.f, 0.f, 0.f, 0.f);
    int stride = gridDim.x * blockDim.x;
    for (int i = blockIdx.x * blockDim.x + threadIdx.x; i < n4; i += stride) {
        reinterpret_cast<float4*>(g_SO)[i] = z;
        reinterpret_cast<float4*>(g_SI)[i] = z;
    }
    int t = blockIdx.x * blockDim.x + threadIdx.x;
    if (t < D) { g_sum[t] = 0.f; g_sumsq[t] = 0.f; }
}

// ---------------- r_ext = concat(r, loop_rel) ----------------
__global__ void build_rext(const float* __restrict__ r_in,
                           const float* __restrict__ loop_rel, int layer) {
    int i = blockIdx.x * blockDim.x + threadIdx.x;
    const float* r = layer ? g_rnext : r_in;
    if (i < NUM_REL * D)      g_rext[i] = r[i];
    else if (i < REXT * D)    g_rext[i] = loop_rel[i - NUM_REL * D];
}

// ---------------- edge scatter: comp_h = n[src]*r_ext[etype]*norm, red into S_O/S_I ----------------
// half-warp (16 lanes) per edge, float4 per lane (64 floats = 256B coalesced)
__global__ __launch_bounds__(256) void edge_scatter(
    const float* __restrict__ nfeat_in0,
    const int*   __restrict__ src,
    const int*   __restrict__ dst,
    const int*   __restrict__ etype,
    const int*   __restrict__ mask,
    const float* __restrict__ norm,
    int E, int layer)
{
    const float* __restrict__ nf = layer ? g_nbuf : nfeat_in0;
    int gid = blockIdx.x * blockDim.x + threadIdx.x;
    int e = gid >> 4;
    if (e >= E) return;
    int c = (gid & 15) * 4;

    int s  = __ldg(src + e);
    int d  = __ldg(dst + e);
    int t  = __ldg(etype + e);
    int m  = __ldg(mask + e);
    float nm = __ldg(norm + e);

    float4 nv = __ldg(reinterpret_cast<const float4*>(nf + s * D + c));
    float4 rv = __ldg(reinterpret_cast<const float4*>(g_rext + t * D + c));

    float4 cm;
    cm.x = nv.x * rv.x * nm;
    cm.y = nv.y * rv.y * nm;
    cm.z = nv.z * rv.z * nm;
    cm.w = nv.w * rv.w * nm;

    float* base = (m ? g_SO : g_SI) + (size_t)d * D + c;
    asm volatile("red.global.add.v4.f32 [%0], {%1,%2,%3,%4};"
                 :: "l"(base), "f"(cm.x), "f"(cm.y), "f"(cm.z), "f"(cm.w)
                 : "memory");
}

// ---------------- node transform: fused 3-way GEMM + BN stats ----------------
// out = (n .* lr) @ W_S^T + S_O @ W_O^T + S_I @ W_I^T, all * 1/3
// W's transposed (lr, 1/3 folded) in SMEM. Warp per 4 rows: weight LDS amortized
// 4x across rows; x fetched as broadcast LDG.128. Lane owns 2 output cols.
__global__ __launch_bounds__(256) void node_transform(
    const float* __restrict__ nfeat_in0,
    const float* __restrict__ WS, const float* __restrict__ WO,
    const float* __restrict__ WI, const float* __restrict__ LR,
    int rows, int layer)
{
    __shared__ float sWS[D * D];
    __shared__ float sWO[D * D];
    __shared__ float sWI[D * D];
    const float third = 1.0f / 3.0f;
    for (int i = threadIdx.x; i < D * D; i += 256) {
        int j = i >> 6, k = i & 63;
        sWS[k * D + j] = __ldg(WS + i) * __ldg(LR + k) * third;
        sWO[k * D + j] = __ldg(WO + i) * third;
        sWI[k * D + j] = __ldg(WI + i) * third;
    }
    __syncthreads();

    const float* __restrict__ nf = layer ? g_nbuf : nfeat_in0;
    int lane   = threadIdx.x & 31;
    int warp   = (blockIdx.x * 256 + threadIdx.x) >> 5;
    int nwarps = (gridDim.x * 256) >> 5;
    int j0 = lane * 2;

    float s0 = 0.f, s1 = 0.f, q0 = 0.f, q1 = 0.f;

    for (int row0 = warp * 4; row0 < rows; row0 += nwarps * 4) {
        float a[4][2] = {{0.f,0.f},{0.f,0.f},{0.f,0.f},{0.f,0.f}};

        if (row0 + 3 < rows) {
            const float4* xn = reinterpret_cast<const float4*>(nf   + (size_t)row0 * D);
            const float4* xo = reinterpret_cast<const float4*>(g_SO + (size_t)row0 * D);
            const float4* xi = reinterpret_cast<const float4*>(g_SI + (size_t)row0 * D);

#pragma unroll 2
            for (int kk = 0; kk < 16; kk++) {      // k-chunk of 4
                float4 vn[4], vo[4], vi[4];
#pragma unroll
                for (int r = 0; r < 4; r++) {
                    vn[r] = __ldg(xn + r * 16 + kk);
                    vo[r] = __ldg(xo + r * 16 + kk);
                    vi[r] = __ldg(xi + r * 16 + kk);
                }
#pragma unroll
                for (int kq = 0; kq < 4; kq++) {
                    int k = kk * 4 + kq;
                    float2 ws = *reinterpret_cast<const float2*>(sWS + k * D + j0);
                    float2 wo = *reinterpret_cast<const float2*>(sWO + k * D + j0);
                    float2 wi = *reinterpret_cast<const float2*>(sWI + k * D + j0);
#pragma unroll
                    for (int r = 0; r < 4; r++) {
                        float n_ = (&vn[r].x)[kq];
                        float o_ = (&vo[r].x)[kq];
                        float i_ = (&vi[r].x)[kq];
                        a[r][0] += n_ * ws.x + o_ * wo.x + i_ * wi.x;
                        a[r][1] += n_ * ws.y + o_ * wo.y + i_ * wi.y;
                    }
                }
            }
#pragma unroll
            for (int r = 0; r < 4; r++) {
                float2 st; st.x = a[r][0]; st.y = a[r][1];
                *reinterpret_cast<float2*>(g_ntmp + (size_t)(row0 + r) * D + j0) = st;
                s0 += a[r][0]; s1 += a[r][1];
                q0 += a[r][0] * a[r][0]; q1 += a[r][1] * a[r][1];
            }
        } else {
            // tail (not hit for rows % 4 == 0, kept for safety)
            for (int r = 0; r < 4 && row0 + r < rows; r++) {
                int row = row0 + r;
                const float* xn = nf   + (size_t)row * D;
                const float* xo = g_SO + (size_t)row * D;
                const float* xi = g_SI + (size_t)row * D;
                float b0 = 0.f, b1 = 0.f;
                for (int k = 0; k < D; k++) {
                    float n_ = __ldg(xn + k), o_ = __ldg(xo + k), i_ = __ldg(xi + k);
                    float2 ws = *reinterpret_cast<const float2*>(sWS + k * D + j0);
                    float2 wo = *reinterpret_cast<const float2*>(sWO + k * D + j0);
                    float2 wi = *reinterpret_cast<const float2*>(sWI + k * D + j0);
                    b0 += n_ * ws.x + o_ * wo.x + i_ * wi.x;
                    b1 += n_ * ws.y + o_ * wo.y + i_ * wi.y;
                }
                float2 st; st.x = b0; st.y = b1;
                *reinterpret_cast<float2*>(g_ntmp + (size_t)row * D + j0) = st;
                s0 += b0; s1 += b1; q0 += b0 * b0; q1 += b1 * b1;
            }
        }
    }

    atomicAdd(&g_sum[j0],       s0);
    atomicAdd(&g_sum[j0 + 1],   s1);
    atomicAdd(&g_sumsq[j0],     q0);
    atomicAdd(&g_sumsq[j0 + 1], q1);
}

// ---------------- BN finalize: fold mean/var/gamma/beta into scale+shift ----------------
__global__ void bn_finalize(const float* __restrict__ gamma,
                            const float* __restrict__ beta, int N) {
    int j = threadIdx.x;
    if (j >= D) return;
    float invN = 1.0f / (float)N;
    float mean = g_sum[j] * invN;
    float var  = fmaxf(g_sumsq[j] * invN - mean * mean, 0.f);
    float rstd = rsqrtf(var + BN_EPS);
    float g = __ldg(gamma + j);
    g_scale[j] = rstd * g;
    g_shift[j] = __ldg(beta + j) - mean * rstd * g;
}

// ---------------- BN apply + tanh ----------------
__global__ __launch_bounds__(256) void bn_apply(float* __restrict__ out_n, int n4, int layer) {
    int i = blockIdx.x * blockDim.x + threadIdx.x;
    if (i >= n4) return;
    float* dst = layer ? out_n : g_nbuf;
    int col = (i & 15) * 4;
    float4 x  = reinterpret_cast<const float4*>(g_ntmp)[i];
    float4 sc = *reinterpret_cast<const float4*>(g_scale + col);
    float4 sh = *reinterpret_cast<const float4*>(g_shift + col);
    float4 y;
    y.x = tanhf(x.x * sc.x + sh.x);
    y.y = tanhf(x.y * sc.y + sh.y);
    y.z = tanhf(x.z * sc.z + sh.z);
    y.w = tanhf(x.w * sc.w + sh.w);
    reinterpret_cast<float4*>(dst)[i] = y;
}

// ---------------- relation update: r_next = (r_ext @ W_R^T)[:-1] ----------------
__global__ __launch_bounds__(256) void rel_update(const float* __restrict__ WR,
                                                  float* __restrict__ out_r, int layer) {
    int g = blockIdx.x * blockDim.x + threadIdx.x;
    int t = g >> 5;
    if (t >= NUM_REL) return;
    int lane = g & 31;
    int j0 = lane * 2;
    float* dst = layer ? out_r : g_rnext;
    float a0 = 0.f, a1 = 0.f;
#pragma unroll 8
    for (int k = 0; k < D; k++) {
        float v = g_rext[t * D + k];
        a0 += v * __ldg(WR + j0 * D + k);
        a1 += v * __ldg(WR + (j0 + 1) * D + k);
    }
    dst[t * D + j0]     = a0;
    dst[t * D + j0 + 1] = a1;
}

// ---------------- launch ----------------
extern "C" void kernel_launch(void* const* d_in, const int* in_sizes, int n_in,
                              void* d_out, int out_size) {
    const float* n0   = (const float*)d_in[0];
    const float* r0   = (const float*)d_in[1];
    const float* norm = (const float*)d_in[2];
    const int*   src  = (const int*)d_in[3];
    const int*   dst  = (const int*)d_in[4];
    const int*   et   = (const int*)d_in[5];
    const int*   msk  = (const int*)d_in[6];
    const int E    = in_sizes[3];
    const int rows = in_sizes[0] / D;

    float* out   = (float*)d_out;
    float* out_n = out;
    float* out_r = out + (size_t)NUM_ENT * D;

    const int n4 = NUM_ENT * D / 4;

    // one warp handles 4 rows; 8 warps/block
    const int nt_blocks = (rows + 31) / 32;

    for (int l = 0; l < 2; l++) {
        const float* WO = (const float*)d_in[7  + 7 * l];
        const float* WI = (const float*)d_in[8  + 7 * l];
        const float* WS = (const float*)d_in[9  + 7 * l];
        const float* WR = (const float*)d_in[10 + 7 * l];
        const float* LR = (const float*)d_in[11 + 7 * l];
        const float* GA = (const float*)d_in[12 + 7 * l];
        const float* BE = (const float*)d_in[13 + 7 * l];

        zero_kernel<<<512, 256>>>();
        build_rext<<<(REXT * D + 255) / 256, 256>>>(r0, LR, l);
        {
            long long threads = (long long)E * 16;
            int blocks = (int)((threads + 255) / 256);
            edge_scatter<<<blocks, 256>>>(n0, src, dst, et, msk, norm, E, l);
        }
        node_transform<<<nt_blocks, 256>>>(n0, WS, WO, WI, LR, rows, l);
        bn_finalize<<<1, 64>>>(GA, BE, rows);
        bn_apply<<<(n4 + 255) / 256, 256>>>(out_n, n4, l);
        rel_update<<<(NUM_REL * 32 + 255) / 256, 256>>>(WR, out_r, l);
    }
}

// round 3
// speedup vs baseline: 1.6107x; 1.6107x over previous
#include <cuda_runtime.h>

#define NUM_ENT 50000
#define NUM_REL 237
#define REXT    238
#define D       64
#define BN_EPS  1e-5f

#define NT_ROWS 64            // rows per block in node_transform
#define NT_PAD  68            // padded k-stride for smem tiles
#define NT_SMEM (2 * 192 * NT_PAD * 4)   // bytes

// ---------------- device scratch (no allocations allowed) ----------------
__device__ float g_SO[NUM_ENT * D];      // scatter sum, mask=1 edges
__device__ float g_SI[NUM_ENT * D];      // scatter sum, mask=0 edges
__device__ float g_ntmp[NUM_ENT * D];    // pre-BN node output
__device__ float g_nbuf[NUM_ENT * D];    // post-layer-0 node features
__device__ float g_rext[REXT * D];       // [r ; loop_rel]
__device__ float g_rnext[NUM_REL * D];   // layer-0 relation output
__device__ float g_sum[D], g_sumsq[D];   // BN stats accumulators
__device__ float g_scale[D], g_shift[D]; // folded BN affine

// ---------------- zero scatter buffers + stats ----------------
__global__ void zero_kernel() {
    const int n4 = NUM_ENT * D / 4;
    float4 z = make_float4(0.f, 0.f, 0.f, 0.f);
    int stride = gridDim.x * blockDim.x;
    for (int i = blockIdx.x * blockDim.x + threadIdx.x; i < n4; i += stride) {
        reinterpret_cast<float4*>(g_SO)[i] = z;
        reinterpret_cast<float4*>(g_SI)[i] = z;
    }
    int t = blockIdx.x * blockDim.x + threadIdx.x;
    if (t < D) { g_sum[t] = 0.f; g_sumsq[t] = 0.f; }
}

// ---------------- r_ext = concat(r, loop_rel) ----------------
__global__ void build_rext(const float* __restrict__ r_in,
                           const float* __restrict__ loop_rel, int layer) {
    int i = blockIdx.x * blockDim.x + threadIdx.x;
    const float* r = layer ? g_rnext : r_in;
    if (i < NUM_REL * D)      g_rext[i] = r[i];
    else if (i < REXT * D)    g_rext[i] = loop_rel[i - NUM_REL * D];
}

// ---------------- edge scatter ----------------
__global__ __launch_bounds__(256) void edge_scatter(
    const float* __restrict__ nfeat_in0,
    const int*   __restrict__ src,
    const int*   __restrict__ dst,
    const int*   __restrict__ etype,
    const int*   __restrict__ mask,
    const float* __restrict__ norm,
    int E, int layer)
{
    const float* __restrict__ nf = layer ? g_nbuf : nfeat_in0;
    int gid = blockIdx.x * blockDim.x + threadIdx.x;
    int e = gid >> 4;
    if (e >= E) return;
    int c = (gid & 15) * 4;

    int s  = __ldg(src + e);
    int d  = __ldg(dst + e);
    int t  = __ldg(etype + e);
    int m  = __ldg(mask + e);
    float nm = __ldg(norm + e);

    float4 nv = __ldg(reinterpret_cast<const float4*>(nf + s * D + c));
    float4 rv = __ldg(reinterpret_cast<const float4*>(g_rext + t * D + c));

    float4 cm;
    cm.x = nv.x * rv.x * nm;
    cm.y = nv.y * rv.y * nm;
    cm.z = nv.z * rv.z * nm;
    cm.w = nv.w * rv.w * nm;

    float* base = (m ? g_SO : g_SI) + (size_t)d * D + c;
    asm volatile("red.global.add.v4.f32 [%0], {%1,%2,%3,%4};"
                 :: "l"(base), "f"(cm.x), "f"(cm.y), "f"(cm.z), "f"(cm.w)
                 : "memory");
}

// ---------------- node transform: tiled SGEMM, [rows x 192] @ [192 x 64] ----------------
// out = (n .* lr) @ W_S^T + S_O @ W_O^T + S_I @ W_I^T, all * 1/3 (folded into sW)
// Block: 64 rows x 64 cols, 256 threads, thread = 4x4 register tile.
// sX[k][row] transposed (pad 68), sW[k][col] fused (pad 68).
__global__ __launch_bounds__(256) void node_transform(
    const float* __restrict__ nfeat_in0,
    const float* __restrict__ WS, const float* __restrict__ WO,
    const float* __restrict__ WI, const float* __restrict__ LR,
    int rows, int layer)
{
    extern __shared__ float smem[];
    float* sW = smem;                 // [192 * NT_PAD]
    float* sX = smem + 192 * NT_PAD;  // [192 * NT_PAD]

    const float* __restrict__ nf = layer ? g_nbuf : nfeat_in0;
    const int tid = threadIdx.x;
    const int tr  = tid >> 4;     // 0..15 -> rows tr*4..tr*4+3
    const int tc  = tid & 15;     // 0..15 -> cols tc*4..tc*4+3
    const int row0 = blockIdx.x * NT_ROWS;
    const float third = 1.0f / 3.0f;

    // ---- stage W (fused scale), transposed to [k][c] ----
    const float* wsrc[3] = {WS, WO, WI};
#pragma unroll
    for (int s = 0; s < 3; s++) {
        for (int i4 = tid; i4 < 1024; i4 += 256) {
            int c  = i4 >> 4;
            int k4 = (i4 & 15) * 4;
            float4 w = __ldg(reinterpret_cast<const float4*>(wsrc[s] + c * D + k4));
            float m0 = third, m1 = third, m2 = third, m3 = third;
            if (s == 0) {
                m0 *= __ldg(LR + k4);     m1 *= __ldg(LR + k4 + 1);
                m2 *= __ldg(LR + k4 + 2); m3 *= __ldg(LR + k4 + 3);
            }
            int kb = s * 64 + k4;
            sW[(kb + 0) * NT_PAD + c] = w.x * m0;
            sW[(kb + 1) * NT_PAD + c] = w.y * m1;
            sW[(kb + 2) * NT_PAD + c] = w.z * m2;
            sW[(kb + 3) * NT_PAD + c] = w.w * m3;
        }
    }

    // ---- stage X transposed to [k][row] ----
    const float* xsrc[3] = {nf, g_SO, g_SI};
#pragma unroll
    for (int s = 0; s < 3; s++) {
        for (int i4 = tid; i4 < 1024; i4 += 256) {
            int row = i4 >> 4;
            int k4  = (i4 & 15) * 4;
            int grow = row0 + row;
            float4 v = make_float4(0.f, 0.f, 0.f, 0.f);
            if (grow < rows)
                v = __ldg(reinterpret_cast<const float4*>(xsrc[s] + (size_t)grow * D + k4));
            int kb = s * 64 + k4;
            sX[(kb + 0) * NT_PAD + row] = v.x;
            sX[(kb + 1) * NT_PAD + row] = v.y;
            sX[(kb + 2) * NT_PAD + row] = v.z;
            sX[(kb + 3) * NT_PAD + row] = v.w;
        }
    }
    __syncthreads();

    // ---- main loop ----
    float acc[4][4];
#pragma unroll
    for (int r = 0; r < 4; r++)
#pragma unroll
        for (int c = 0; c < 4; c++) acc[r][c] = 0.f;

    const int xoff = tr * 4;
    const int woff = tc * 4;
#pragma unroll 8
    for (int k = 0; k < 192; k++) {
        float4 xv = *reinterpret_cast<const float4*>(sX + k * NT_PAD + xoff);
        float4 wv = *reinterpret_cast<const float4*>(sW + k * NT_PAD + woff);
        const float xr[4] = {xv.x, xv.y, xv.z, xv.w};
        const float wc[4] = {wv.x, wv.y, wv.z, wv.w};
#pragma unroll
        for (int r = 0; r < 4; r++)
#pragma unroll
            for (int c = 0; c < 4; c++)
                acc[r][c] += xr[r] * wc[c];
    }

    // ---- store outputs + per-thread stats ----
    float s_[4] = {0.f, 0.f, 0.f, 0.f};
    float q_[4] = {0.f, 0.f, 0.f, 0.f};
#pragma unroll
    for (int r = 0; r < 4; r++) {
        int grow = row0 + tr * 4 + r;
        if (grow < rows) {
            float4 o;
            o.x = acc[r][0]; o.y = acc[r][1]; o.z = acc[r][2]; o.w = acc[r][3];
            *reinterpret_cast<float4*>(g_ntmp + (size_t)grow * D + woff) = o;
#pragma unroll
            for (int c = 0; c < 4; c++) {
                s_[c] += acc[r][c];
                q_[c] += acc[r][c] * acc[r][c];
            }
        }
    }

    // ---- block reduce stats (reuse sX region) ----
    __syncthreads();
    float* redS = sX;          // [64 cols][16 tr]
    float* redQ = sX + 1024;
#pragma unroll
    for (int c = 0; c < 4; c++) {
        redS[(woff + c) * 16 + tr] = s_[c];
        redQ[(woff + c) * 16 + tr] = q_[c];
    }
    __syncthreads();
    if (tid < D) {
        float ss = 0.f, qq = 0.f;
#pragma unroll
        for (int t = 0; t < 16; t++) {
            ss += redS[tid * 16 + t];
            qq += redQ[tid * 16 + t];
        }
        atomicAdd(&g_sum[tid],   ss);
        atomicAdd(&g_sumsq[tid], qq);
    }
}

// ---------------- BN finalize ----------------
__global__ void bn_finalize(const float* __restrict__ gamma,
                            const float* __restrict__ beta, int N) {
    int j = threadIdx.x;
    if (j >= D) return;
    float invN = 1.0f / (float)N;
    float mean = g_sum[j] * invN;
    float var  = fmaxf(g_sumsq[j] * invN - mean * mean, 0.f);
    float rstd = rsqrtf(var + BN_EPS);
    float g = __ldg(gamma + j);
    g_scale[j] = rstd * g;
    g_shift[j] = __ldg(beta + j) - mean * rstd * g;
}

// ---------------- BN apply + tanh ----------------
__global__ __launch_bounds__(256) void bn_apply(float* __restrict__ out_n, int n4, int layer) {
    int i = blockIdx.x * blockDim.x + threadIdx.x;
    if (i >= n4) return;
    float* dst = layer ? out_n : g_nbuf;
    int col = (i & 15) * 4;
    float4 x  = reinterpret_cast<const float4*>(g_ntmp)[i];
    float4 sc = *reinterpret_cast<const float4*>(g_scale + col);
    float4 sh = *reinterpret_cast<const float4*>(g_shift + col);
    float4 y;
    y.x = tanhf(x.x * sc.x + sh.x);
    y.y = tanhf(x.y * sc.y + sh.y);
    y.z = tanhf(x.z * sc.z + sh.z);
    y.w = tanhf(x.w * sc.w + sh.w);
    reinterpret_cast<float4*>(dst)[i] = y;
}

// ---------------- relation update: r_next = (r_ext @ W_R^T)[:-1] ----------------
__global__ __launch_bounds__(256) void rel_update(const float* __restrict__ WR,
                                                  float* __restrict__ out_r, int layer) {
    int g = blockIdx.x * blockDim.x + threadIdx.x;
    int t = g >> 5;
    if (t >= NUM_REL) return;
    int lane = g & 31;
    int j0 = lane * 2;
    float* dst = layer ? out_r : g_rnext;
    float a0 = 0.f, a1 = 0.f;
#pragma unroll 8
    for (int k = 0; k < D; k++) {
        float v = g_rext[t * D + k];
        a0 += v * __ldg(WR + j0 * D + k);
        a1 += v * __ldg(WR + (j0 + 1) * D + k);
    }
    dst[t * D + j0]     = a0;
    dst[t * D + j0 + 1] = a1;
}

// ---------------- launch ----------------
extern "C" void kernel_launch(void* const* d_in, const int* in_sizes, int n_in,
                              void* d_out, int out_size) {
    const float* n0   = (const float*)d_in[0];
    const float* r0   = (const float*)d_in[1];
    const float* norm = (const float*)d_in[2];
    const int*   src  = (const int*)d_in[3];
    const int*   dst  = (const int*)d_in[4];
    const int*   et   = (const int*)d_in[5];
    const int*   msk  = (const int*)d_in[6];
    const int E    = in_sizes[3];
    const int rows = in_sizes[0] / D;

    float* out   = (float*)d_out;
    float* out_n = out;
    float* out_r = out + (size_t)NUM_ENT * D;

    const int n4 = NUM_ENT * D / 4;

    static int smem_set = 0;
    if (!smem_set) {
        cudaFuncSetAttribute(node_transform,
                             cudaFuncAttributeMaxDynamicSharedMemorySize, NT_SMEM);
        smem_set = 1;
    }

    const int nt_blocks = (rows + NT_ROWS - 1) / NT_ROWS;

    for (int l = 0; l < 2; l++) {
        const float* WO = (const float*)d_in[7  + 7 * l];
        const float* WI = (const float*)d_in[8  + 7 * l];
        const float* WS = (const float*)d_in[9  + 7 * l];
        const float* WR = (const float*)d_in[10 + 7 * l];
        const float* LR = (const float*)d_in[11 + 7 * l];
        const float* GA = (const float*)d_in[12 + 7 * l];
        const float* BE = (const float*)d_in[13 + 7 * l];

        zero_kernel<<<512, 256>>>();
        build_rext<<<(REXT * D + 255) / 256, 256>>>(r0, LR, l);
        {
            long long threads = (long long)E * 16;
            int blocks = (int)((threads + 255) / 256);
            edge_scatter<<<blocks, 256>>>(n0, src, dst, et, msk, norm, E, l);
        }
        node_transform<<<nt_blocks, 256, NT_SMEM>>>(n0, WS, WO, WI, LR, rows, l);
        bn_finalize<<<1, 64>>>(GA, BE, rows);
        bn_apply<<<(n4 + 255) / 256, 256>>>(out_n, n4, l);
        rel_update<<<(NUM_REL * 32 + 255) / 256, 256>>>(WR, out_r, l);
    }
}

// round 4
// speedup vs baseline: 1.7021x; 1.0567x over previous
#include <cuda_runtime.h>

#define NUM_ENT 50000
#define NUM_REL 237
#define REXT    238
#define D       64
#define BN_EPS  1e-5f

#define NT_ROWS 64
#define NT_PAD  68
#define NT_SMEM (2 * 192 * NT_PAD * 4)   // 104.4 KB

// ---------------- device scratch ----------------
__device__ float g_SO[NUM_ENT * D];
__device__ float g_SI[NUM_ENT * D];
__device__ float g_ntmp[NUM_ENT * D];
__device__ float g_nbuf[NUM_ENT * D];
__device__ float g_rext[REXT * D];
__device__ float g_rnext[NUM_REL * D];
__device__ float g_sum[D], g_sumsq[D];
__device__ float g_scale[D], g_shift[D];

// ---- f32x2 packed helpers ----
__device__ __forceinline__ void fma2(unsigned long long& d,
                                     unsigned long long a,
                                     unsigned long long b) {
    asm("fma.rn.f32x2 %0, %1, %2, %0;" : "+l"(d) : "l"(a), "l"(b));
}
__device__ __forceinline__ unsigned long long pack2(float lo, float hi) {
    unsigned long long p;
    asm("mov.b64 %0, {%1, %2};" : "=l"(p) : "f"(lo), "f"(hi));
    return p;
}
__device__ __forceinline__ void unpack2(unsigned long long p, float& lo, float& hi) {
    asm("mov.b64 {%0, %1}, %2;" : "=f"(lo), "=f"(hi) : "l"(p));
}

// ---------------- zero scatter buffers + stats ----------------
__global__ void zero_kernel() {
    const int n4 = NUM_ENT * D / 4;
    float4 z = make_float4(0.f, 0.f, 0.f, 0.f);
    int stride = gridDim.x * blockDim.x;
    for (int i = blockIdx.x * blockDim.x + threadIdx.x; i < n4; i += stride) {
        reinterpret_cast<float4*>(g_SO)[i] = z;
        reinterpret_cast<float4*>(g_SI)[i] = z;
    }
    int t = blockIdx.x * blockDim.x + threadIdx.x;
    if (t < D) { g_sum[t] = 0.f; g_sumsq[t] = 0.f; }
}

// ---------------- r_ext = concat(r, loop_rel) ----------------
__global__ void build_rext(const float* __restrict__ r_in,
                           const float* __restrict__ loop_rel, int layer) {
    int i = blockIdx.x * blockDim.x + threadIdx.x;
    const float* r = layer ? g_rnext : r_in;
    if (i < NUM_REL * D)      g_rext[i] = r[i];
    else if (i < REXT * D)    g_rext[i] = loop_rel[i - NUM_REL * D];
}

// ---------------- edge scatter ----------------
__global__ __launch_bounds__(256) void edge_scatter(
    const float* __restrict__ nfeat_in0,
    const int*   __restrict__ src,
    const int*   __restrict__ dst,
    const int*   __restrict__ etype,
    const int*   __restrict__ mask,
    const float* __restrict__ norm,
    int E, int layer)
{
    const float* __restrict__ nf = layer ? g_nbuf : nfeat_in0;
    int gid = blockIdx.x * blockDim.x + threadIdx.x;
    int e = gid >> 4;
    if (e >= E) return;
    int c = (gid & 15) * 4;

    int s  = __ldg(src + e);
    int d  = __ldg(dst + e);
    int t  = __ldg(etype + e);
    int m  = __ldg(mask + e);
    float nm = __ldg(norm + e);

    float4 nv = __ldg(reinterpret_cast<const float4*>(nf + s * D + c));
    float4 rv = __ldg(reinterpret_cast<const float4*>(g_rext + t * D + c));

    float4 cm;
    cm.x = nv.x * rv.x * nm;
    cm.y = nv.y * rv.y * nm;
    cm.z = nv.z * rv.z * nm;
    cm.w = nv.w * rv.w * nm;

    float* base = (m ? g_SO : g_SI) + (size_t)d * D + c;
    asm volatile("red.global.add.v4.f32 [%0], {%1,%2,%3,%4};"
                 :: "l"(base), "f"(cm.x), "f"(cm.y), "f"(cm.z), "f"(cm.w)
                 : "memory");
}

// ---------------- node transform: tiled GEMM w/ packed f32x2 FMA ----------------
// Block 64 rows x 64 cols, 128 threads; thread = 8 rows x 4 cols.
// Rows paired into f32x2 (fall straight out of LDS.128); weights duplicated {w,w}.
__global__ __launch_bounds__(128) void node_transform(
    const float* __restrict__ nfeat_in0,
    const float* __restrict__ WS, const float* __restrict__ WO,
    const float* __restrict__ WI, const float* __restrict__ LR,
    int rows, int layer)
{
    extern __shared__ float smem[];
    float* sW = smem;                 // [192][NT_PAD]
    float* sX = smem + 192 * NT_PAD;  // [192][NT_PAD]

    const float* __restrict__ nf = layer ? g_nbuf : nfeat_in0;
    const int tid = threadIdx.x;       // 128 threads
    const int tr  = tid >> 4;          // 0..7  -> rows tr*8..tr*8+7
    const int tc  = tid & 15;          // 0..15 -> cols tc*4..tc*4+3
    const int row0 = blockIdx.x * NT_ROWS;
    const float third = 1.0f / 3.0f;

    // ---- stage W (fused lr & 1/3), transposed to [k][c] ----
    const float* wsrc[3] = {WS, WO, WI};
#pragma unroll
    for (int s = 0; s < 3; s++) {
        for (int i4 = tid; i4 < 1024; i4 += 128) {
            int c  = i4 >> 4;
            int k4 = (i4 & 15) * 4;
            float4 w = __ldg(reinterpret_cast<const float4*>(wsrc[s] + c * D + k4));
            float m0 = third, m1 = third, m2 = third, m3 = third;
            if (s == 0) {
                m0 *= __ldg(LR + k4);     m1 *= __ldg(LR + k4 + 1);
                m2 *= __ldg(LR + k4 + 2); m3 *= __ldg(LR + k4 + 3);
            }
            int kb = s * 64 + k4;
            sW[(kb + 0) * NT_PAD + c] = w.x * m0;
            sW[(kb + 1) * NT_PAD + c] = w.y * m1;
            sW[(kb + 2) * NT_PAD + c] = w.z * m2;
            sW[(kb + 3) * NT_PAD + c] = w.w * m3;
        }
    }

    // ---- stage X transposed to [k][row] ----
    const float* xsrc[3] = {nf, g_SO, g_SI};
#pragma unroll
    for (int s = 0; s < 3; s++) {
        for (int i4 = tid; i4 < 1024; i4 += 128) {
            int row = i4 >> 4;
            int k4  = (i4 & 15) * 4;
            int grow = row0 + row;
            float4 v = make_float4(0.f, 0.f, 0.f, 0.f);
            if (grow < rows)
                v = __ldg(reinterpret_cast<const float4*>(xsrc[s] + (size_t)grow * D + k4));
            int kb = s * 64 + k4;
            sX[(kb + 0) * NT_PAD + row] = v.x;
            sX[(kb + 1) * NT_PAD + row] = v.y;
            sX[(kb + 2) * NT_PAD + row] = v.z;
            sX[(kb + 3) * NT_PAD + row] = v.w;
        }
    }
    __syncthreads();

    // ---- main loop: acc2[rp][c] = row-pair (2rp,2rp+1) x col c ----
    unsigned long long acc2[4][4];
#pragma unroll
    for (int rp = 0; rp < 4; rp++)
#pragma unroll
        for (int c = 0; c < 4; c++) acc2[rp][c] = 0ULL;

    const float* xbase = sX + tr * 8;
    const float* wbase = sW + tc * 4;

#pragma unroll 4
    for (int k = 0; k < 192; k++) {
        float4 xv0 = *reinterpret_cast<const float4*>(xbase + k * NT_PAD);
        float4 xv1 = *reinterpret_cast<const float4*>(xbase + k * NT_PAD + 4);
        float4 wv  = *reinterpret_cast<const float4*>(wbase + k * NT_PAD);

        unsigned long long xp[4];
        xp[0] = pack2(xv0.x, xv0.y);
        xp[1] = pack2(xv0.z, xv0.w);
        xp[2] = pack2(xv1.x, xv1.y);
        xp[3] = pack2(xv1.z, xv1.w);

        unsigned long long wd[4];
        wd[0] = pack2(wv.x, wv.x);
        wd[1] = pack2(wv.y, wv.y);
        wd[2] = pack2(wv.z, wv.z);
        wd[3] = pack2(wv.w, wv.w);

#pragma unroll
        for (int rp = 0; rp < 4; rp++)
#pragma unroll
            for (int c = 0; c < 4; c++)
                fma2(acc2[rp][c], xp[rp], wd[c]);
    }

    // ---- store + per-thread BN partial stats ----
    const int woff = tc * 4;
    float s_[4] = {0.f, 0.f, 0.f, 0.f};
    float q_[4] = {0.f, 0.f, 0.f, 0.f};
#pragma unroll
    for (int rp = 0; rp < 4; rp++) {
        float lo[4], hi[4];
#pragma unroll
        for (int c = 0; c < 4; c++) unpack2(acc2[rp][c], lo[c], hi[c]);
        int r0g = row0 + tr * 8 + rp * 2;
        if (r0g < rows) {
            float4 o; o.x = lo[0]; o.y = lo[1]; o.z = lo[2]; o.w = lo[3];
            *reinterpret_cast<float4*>(g_ntmp + (size_t)r0g * D + woff) = o;
#pragma unroll
            for (int c = 0; c < 4; c++) { s_[c] += lo[c]; q_[c] += lo[c] * lo[c]; }
        }
        if (r0g + 1 < rows) {
            float4 o; o.x = hi[0]; o.y = hi[1]; o.z = hi[2]; o.w = hi[3];
            *reinterpret_cast<float4*>(g_ntmp + (size_t)(r0g + 1) * D + woff) = o;
#pragma unroll
            for (int c = 0; c < 4; c++) { s_[c] += hi[c]; q_[c] += hi[c] * hi[c]; }
        }
    }

    // ---- block reduce stats (reuse sX region) ----
    __syncthreads();
    float* redS = sX;          // [64 cols][8 tr]
    float* redQ = sX + 512;
#pragma unroll
    for (int c = 0; c < 4; c++) {
        redS[(woff + c) * 8 + tr] = s_[c];
        redQ[(woff + c) * 8 + tr] = q_[c];
    }
    __syncthreads();
    if (tid < D) {
        float ss = 0.f, qq = 0.f;
#pragma unroll
        for (int t = 0; t < 8; t++) {
            ss += redS[tid * 8 + t];
            qq += redQ[tid * 8 + t];
        }
        atomicAdd(&g_sum[tid],   ss);
        atomicAdd(&g_sumsq[tid], qq);
    }
}

// ---------------- BN finalize ----------------
__global__ void bn_finalize(const float* __restrict__ gamma,
                            const float* __restrict__ beta, int N) {
    int j = threadIdx.x;
    if (j >= D) return;
    float invN = 1.0f / (float)N;
    float mean = g_sum[j] * invN;
    float var  = fmaxf(g_sumsq[j] * invN - mean * mean, 0.f);
    float rstd = rsqrtf(var + BN_EPS);
    float g = __ldg(gamma + j);
    g_scale[j] = rstd * g;
    g_shift[j] = __ldg(beta + j) - mean * rstd * g;
}

// ---------------- BN apply + tanh ----------------
__global__ __launch_bounds__(256) void bn_apply(float* __restrict__ out_n, int n4, int layer) {
    int i = blockIdx.x * blockDim.x + threadIdx.x;
    if (i >= n4) return;
    float* dst = layer ? out_n : g_nbuf;
    int col = (i & 15) * 4;
    float4 x  = reinterpret_cast<const float4*>(g_ntmp)[i];
    float4 sc = *reinterpret_cast<const float4*>(g_scale + col);
    float4 sh = *reinterpret_cast<const float4*>(g_shift + col);
    float4 y;
    y.x = tanhf(x.x * sc.x + sh.x);
    y.y = tanhf(x.y * sc.y + sh.y);
    y.z = tanhf(x.z * sc.z + sh.z);
    y.w = tanhf(x.w * sc.w + sh.w);
    reinterpret_cast<float4*>(dst)[i] = y;
}

// ---------------- relation update ----------------
__global__ __launch_bounds__(256) void rel_update(const float* __restrict__ WR,
                                                  float* __restrict__ out_r, int layer) {
    int g = blockIdx.x * blockDim.x + threadIdx.x;
    int t = g >> 5;
    if (t >= NUM_REL) return;
    int lane = g & 31;
    int j0 = lane * 2;
    float* dst = layer ? out_r : g_rnext;
    float a0 = 0.f, a1 = 0.f;
#pragma unroll 8
    for (int k = 0; k < D; k++) {
        float v = g_rext[t * D + k];
        a0 += v * __ldg(WR + j0 * D + k);
        a1 += v * __ldg(WR + (j0 + 1) * D + k);
    }
    dst[t * D + j0]     = a0;
    dst[t * D + j0 + 1] = a1;
}

// ---------------- launch ----------------
extern "C" void kernel_launch(void* const* d_in, const int* in_sizes, int n_in,
                              void* d_out, int out_size) {
    const float* n0   = (const float*)d_in[0];
    const float* r0   = (const float*)d_in[1];
    const float* norm = (const float*)d_in[2];
    const int*   src  = (const int*)d_in[3];
    const int*   dst  = (const int*)d_in[4];
    const int*   et   = (const int*)d_in[5];
    const int*   msk  = (const int*)d_in[6];
    const int E    = in_sizes[3];
    const int rows = in_sizes[0] / D;

    float* out   = (float*)d_out;
    float* out_n = out;
    float* out_r = out + (size_t)NUM_ENT * D;

    const int n4 = NUM_ENT * D / 4;

    static int smem_set = 0;
    if (!smem_set) {
        cudaFuncSetAttribute(node_transform,
                             cudaFuncAttributeMaxDynamicSharedMemorySize, NT_SMEM);
        smem_set = 1;
    }

    const int nt_blocks = (rows + NT_ROWS - 1) / NT_ROWS;

    for (int l = 0; l < 2; l++) {
        const float* WO = (const float*)d_in[7  + 7 * l];
        const float* WI = (const float*)d_in[8  + 7 * l];
        const float* WS = (const float*)d_in[9  + 7 * l];
        const float* WR = (const float*)d_in[10 + 7 * l];
        const float* LR = (const float*)d_in[11 + 7 * l];
        const float* GA = (const float*)d_in[12 + 7 * l];
        const float* BE = (const float*)d_in[13 + 7 * l];

        zero_kernel<<<512, 256>>>();
        build_rext<<<(REXT * D + 255) / 256, 256>>>(r0, LR, l);
        {
            long long threads = (long long)E * 16;
            int blocks = (int)((threads + 255) / 256);
            edge_scatter<<<blocks, 256>>>(n0, src, dst, et, msk, norm, E, l);
        }
        node_transform<<<nt_blocks, 128, NT_SMEM>>>(n0, WS, WO, WI, LR, rows, l);
        bn_finalize<<<1, 64>>>(GA, BE, rows);
        bn_apply<<<(n4 + 255) / 256, 256>>>(out_n, n4, l);
        rel_update<<<(NUM_REL * 32 + 255) / 256, 256>>>(WR, out_r, l);
    }
}